// round 11
// baseline (speedup 1.0000x reference)
#include <cuda_runtime.h>
#include <cuda_bf16.h>
#include <math.h>
#include <stdint.h>

#define Zd  128
#define Nd  256
#define Fd  2048
#define Bd  8192
#define OSTRIDE 129   // Z+1

#define TMr 32        // batch rows per CTA
#define BF  64        // f tile
#define NCH 4         // pipeline chunks over F
#define FCH (Fd / NCH)        // 512 f per chunk
#define NTC (FCH / BF)        // 8 tiles per chunk

// ---------------- device scratch ----------------
__device__ float g_h1[4][Nd];
__device__ float g_win  [Fd * Zd];
__device__ float g_wout [Fd * Zd];
__device__ float g_woutT[Zd * Fd];
__device__ float g_bias[Fd];
__device__ float g_gate[Fd];
__device__ float g_gs  [Fd];
__device__ __align__(16) uint16_t g_win_h16[Fd * Zd];   // [f][z]
__device__ __align__(16) uint16_t g_win_l16[Fd * Zd];
__device__ __align__(16) uint16_t g_woT_h16[Zd * Fd];   // [z][f]
__device__ __align__(16) uint16_t g_woT_l16[Zd * Fd];

// ---------------- smem word layout (strides ≡ 4 mod 32, rows 16B-aligned) ----------------
#define STZ 68
#define STG 36
#define O_ZHI   0
#define O_ZLO   (O_ZHI  + TMr * STZ)
#define O_WIH   (O_ZLO  + TMr * STZ)
#define O_WIL   (O_WIH  + BF * STZ)
#define O_WOTH  (O_WIL  + BF * STZ)
#define O_WOTL  (O_WOTH + Zd * STG)
#define O_GHI   (O_WOTL + Zd * STG)
#define O_GLO   (O_GHI  + TMr * STG)
#define O_TRS   (O_GLO  + TMr * STG)
#define SMEMW   (O_TRS  + TMr * 4)
#define SMEM_TC (SMEMW * 4)

// ---------------- helpers ----------------
__device__ __forceinline__ uint32_t smem_u32(const void* p) {
    uint32_t a;
    asm("{ .reg .u64 t; cvta.to.shared.u64 t, %1; cvt.u32.u64 %0, t; }" : "=r"(a) : "l"(p));
    return a;
}
__device__ __forceinline__ void ldsm_x4(uint32_t* r, uint32_t addr) {
    asm volatile("ldmatrix.sync.aligned.m8n8.x4.shared.b16 {%0,%1,%2,%3}, [%4];"
                 : "=r"(r[0]), "=r"(r[1]), "=r"(r[2]), "=r"(r[3]) : "r"(addr));
}

__device__ __forceinline__ uint32_t pack_split(float a, float b, uint32_t& lopack) {
    __nv_bfloat16 ah = __float2bfloat16_rn(a);
    __nv_bfloat16 bh = __float2bfloat16_rn(b);
    __nv_bfloat16 al = __float2bfloat16_rn(a - __bfloat162float(ah));
    __nv_bfloat16 bl = __float2bfloat16_rn(b - __bfloat162float(bh));
    lopack = (uint32_t)__bfloat16_as_ushort(al) | ((uint32_t)__bfloat16_as_ushort(bl) << 16);
    return (uint32_t)__bfloat16_as_ushort(ah) | ((uint32_t)__bfloat16_as_ushort(bh) << 16);
}

__device__ __forceinline__ float fast_tanh(float x) {
    float ax = fabsf(x);
    float e;
    asm("ex2.approx.f32 %0, %1;" : "=f"(e) : "f"(ax * 2.8853900817779268f));
    float r;
    asm("rcp.approx.f32 %0, %1;" : "=f"(r) : "f"(e + 1.0f));
    return copysignf(1.0f - 2.0f * r, x);
}

__device__ __forceinline__ void mma_bf16(float* c, const uint32_t* a, const uint32_t* b) {
    asm volatile(
        "mma.sync.aligned.m16n8k16.row.col.f32.bf16.bf16.f32 "
        "{%0,%1,%2,%3}, {%4,%5,%6,%7}, {%8,%9}, {%0,%1,%2,%3};"
        : "+f"(c[0]), "+f"(c[1]), "+f"(c[2]), "+f"(c[3])
        : "r"(a[0]), "r"(a[1]), "r"(a[2]), "r"(a[3]), "r"(b[0]), "r"(b[1]));
}

// ---------------- kernel 1: hypernet h0 -> h1 (32 blocks) ----------------
__global__ void k_h1(const float* __restrict__ tt,
                     const float* __restrict__ W1, const float* __restrict__ B1,
                     const float* __restrict__ W2, const float* __restrict__ B2) {
    __shared__ float h0[Nd];
    const int k   = blockIdx.x >> 3;
    const int blk = blockIdx.x & 7;
    const int t   = threadIdx.x;
    const float ts = tt[0];
    h0[t] = tanhf(fmaf(W1[k * Nd + t], ts, B1[k * Nd + t]));
    __syncthreads();

    const int wid  = t >> 5;
    const int lane = t & 31;
    const float4* h4 = (const float4*)h0;
#pragma unroll
    for (int r = 0; r < 4; r++) {
        const int n = blk * 32 + wid * 4 + r;
        const float4* w2 = (const float4*)(W2 + ((size_t)k * Nd + n) * Nd);
        float acc = 0.f;
#pragma unroll
        for (int i = 0; i < 2; i++) {
            float4 v = w2[lane + i * 32];
            float4 h = h4[lane + i * 32];
            acc = fmaf(v.x, h.x, fmaf(v.y, h.y, fmaf(v.z, h.z, fmaf(v.w, h.w, acc))));
        }
#pragma unroll
        for (int o = 16; o > 0; o >>= 1) acc += __shfl_xor_sync(0xFFFFFFFFu, acc, o);
        if (lane == 0) g_h1[k][n] = tanhf(acc + B2[k * Nd + n]);
    }
}

// ---------------- kernel 2: w_in / w_out matvecs, f-chunked ----------------
__global__ void k_wproj(int chunk,
                        const float* __restrict__ W3_win,  const float* __restrict__ b3_win,
                        const float* __restrict__ W3_wout, const float* __restrict__ b3_wout) {
    __shared__ float h1a[Nd], h1b[Nd];
    const int t = threadIdx.x;
    h1a[t] = g_h1[0][t];
    h1b[t] = g_h1[1][t];
    __syncthreads();

    const int wid  = t >> 5;
    const int lane = t & 31;
    const int rl   = blockIdx.x * 8 + wid;          // 0 .. 2*FCH*Zd-1
    const int isOut = rl >= FCH * Zd;
    const long rr = (long)chunk * (FCH * Zd) + (rl & (FCH * Zd - 1));

    const float* wmat = isOut ? W3_wout : W3_win;
    const float* bias = isOut ? b3_wout : b3_win;
    const float* hv   = isOut ? h1b : h1a;

    const float4* __restrict__ row = (const float4*)(wmat + rr * Nd);
    const float4* __restrict__ hv4 = (const float4*)hv;
    float acc = 0.f;
#pragma unroll
    for (int i = 0; i < 2; i++) {
        float4 v = row[lane + i * 32];
        float4 h = hv4[lane + i * 32];
        acc = fmaf(v.x, h.x, acc);
        acc = fmaf(v.y, h.y, acc);
        acc = fmaf(v.z, h.z, acc);
        acc = fmaf(v.w, h.w, acc);
    }
#pragma unroll
    for (int o = 16; o > 0; o >>= 1) acc += __shfl_xor_sync(0xFFFFFFFFu, acc, o);
    if (lane == 0) {
        float v = acc + bias[rr];
        if (isOut) {
            g_wout[rr] = v;
            int f = (int)(rr >> 7);
            int z = (int)(rr & 127);
            g_woutT[(size_t)z * Fd + f] = v;
        } else {
            g_win[rr] = v;
        }
    }
}

// ---------------- k_split: bf16 hi/lo presplit, f-chunked ----------------
__global__ void k_split(int chunk) {
    const int i = blockIdx.x * 256 + threadIdx.x;       // 0 .. FCH*Zd-1
    {
        const int idx = chunk * (FCH * Zd) + i;
        float v = g_win[idx];
        __nv_bfloat16 hb = __float2bfloat16_rn(v);
        g_win_h16[idx] = __bfloat16_as_ushort(hb);
        g_win_l16[idx] = __bfloat16_as_ushort(__float2bfloat16_rn(v - __bfloat162float(hb)));
    }
    {
        const int z  = i >> 9;           // 0..127
        const int fl = i & 511;
        const size_t idx = (size_t)z * Fd + chunk * FCH + fl;
        float v = g_woutT[idx];
        __nv_bfloat16 hb = __float2bfloat16_rn(v);
        g_woT_h16[idx] = __bfloat16_as_ushort(hb);
        g_woT_l16[idx] = __bfloat16_as_ushort(__float2bfloat16_rn(v - __bfloat162float(hb)));
    }
}

// ---------------- kernel 3: bias, gate, gate*s, f-chunked ----------------
__global__ void k_small(int chunk,
                        const float* __restrict__ W3_b,    const float* __restrict__ b3_b,
                        const float* __restrict__ W3_gate, const float* __restrict__ b3_gate) {
    __shared__ float h2[Nd], h3[Nd];
    const int t = threadIdx.x;
    h2[t] = g_h1[2][t];  h2[t + 128] = g_h1[2][t + 128];
    h3[t] = g_h1[3][t];  h3[t + 128] = g_h1[3][t + 128];
    __syncthreads();

    const int wid  = t >> 5;
    const int lane = t & 31;
    const int f = chunk * FCH + blockIdx.x * 4 + wid;

    const float4* rb = (const float4*)(W3_b    + (size_t)f * Nd);
    const float4* rg = (const float4*)(W3_gate + (size_t)f * Nd);
    const float4* h2v = (const float4*)h2;
    const float4* h3v = (const float4*)h3;

    float accb = 0.f, accg = 0.f;
#pragma unroll
    for (int i = 0; i < 2; i++) {
        float4 v = rb[lane + i * 32], h = h2v[lane + i * 32];
        accb = fmaf(v.x, h.x, fmaf(v.y, h.y, fmaf(v.z, h.z, fmaf(v.w, h.w, accb))));
        float4 v2 = rg[lane + i * 32], h4 = h3v[lane + i * 32];
        accg = fmaf(v2.x, h4.x, fmaf(v2.y, h4.y, fmaf(v2.z, h4.z, fmaf(v2.w, h4.w, accg))));
    }
    const float4 a  = ((const float4*)(g_win  + (size_t)f * Zd))[lane];
    const float4 b4 = ((const float4*)(g_wout + (size_t)f * Zd))[lane];
    float accs = a.x * b4.x + a.y * b4.y + a.z * b4.z + a.w * b4.w;

#pragma unroll
    for (int o = 16; o > 0; o >>= 1) {
        accb += __shfl_xor_sync(0xFFFFFFFFu, accb, o);
        accg += __shfl_xor_sync(0xFFFFFFFFu, accg, o);
        accs += __shfl_xor_sync(0xFFFFFFFFu, accs, o);
    }
    if (lane == 0) {
        g_bias[f] = accb + b3_b[f];
        float gt = 1.f / (1.f + expf(-(accg + b3_gate[f])));
        g_gate[f] = gt;
        g_gs[f]   = gt * accs;
    }
}

// ---------------- k_tc: bf16x3 mma.sync double GEMM, f-chunked ----------------
__global__ __launch_bounds__(256, 2)
void k_tc(int chunk, const float* __restrict__ zlp, float* __restrict__ out) {
    extern __shared__ uint32_t smw[];
    float* smf = (float*)smw;
    const uint32_t sb = smem_u32(smw);

    const int t    = threadIdx.x;
    const int lane = t & 31;
    const int wid  = t >> 5;
    const int g    = lane >> 2;
    const int tq   = lane & 3;
    const int wr   = wid >> 2;
    const int wc   = wid & 3;
    const int b0   = blockIdx.x * TMr;

    const int rowA  = lane & 15;
    const int aofs  = ((lane >> 4) & 1) * 16;
    const int rowB  = (lane & 7) + ((lane >> 4) & 1) * 8;
    const int bofs  = ((lane >> 3) & 1) * 16;

    const uint32_t aZH = sb + O_ZHI * 4 + (wr * 16 + rowA) * (STZ * 4) + aofs;
    const uint32_t aZL = sb + O_ZLO * 4 + (wr * 16 + rowA) * (STZ * 4) + aofs;
    const uint32_t bWH = sb + O_WIH * 4 + (wc * 16 + rowB) * (STZ * 4) + bofs;
    const uint32_t bWL = sb + O_WIL * 4 + (wc * 16 + rowB) * (STZ * 4) + bofs;
    const uint32_t aGH = sb + O_GHI * 4 + (wr * 16 + rowA) * (STG * 4) + aofs;
    const uint32_t aGL = sb + O_GLO * 4 + (wr * 16 + rowA) * (STG * 4) + aofs;
    const uint32_t bOH0 = sb + O_WOTH * 4 + (wc * 32 + rowB) * (STG * 4) + bofs;
    const uint32_t bOH1 = bOH0 + 16 * (STG * 4);
    const uint32_t bOL0 = sb + O_WOTL * 4 + (wc * 32 + rowB) * (STG * 4) + bofs;
    const uint32_t bOL1 = bOL0 + 16 * (STG * 4);

    // ---- stage z (hi/lo bf16) ----
#pragma unroll
    for (int it = 0; it < 8; it++) {
        int idx = t + it * 256;
        int m = idx >> 6, kp = idx & 63;
        const float* zr = zlp + (size_t)(b0 + m) * OSTRIDE + 2 * kp;
        uint32_t lo, hi = pack_split(zr[0], zr[1], lo);
        smw[O_ZHI + m * STZ + kp] = hi;
        smw[O_ZLO + m * STZ + kp] = lo;
    }

    float dz[4][4];
#pragma unroll
    for (int j = 0; j < 4; j++)
#pragma unroll
        for (int q = 0; q < 4; q++) dz[j][q] = 0.f;
    float tracc[2] = {0.f, 0.f};

    for (int tile = 0; tile < NTC; tile++) {
        const int f0 = chunk * FCH + tile * BF;
        __syncthreads();

#pragma unroll
        for (int it = 0; it < 4; it++) {
            int idx = t + it * 256;
            int fi = idx >> 4, seg = idx & 15;
            *(uint4*)&smw[O_WIH + fi * STZ + seg * 4] =
                *(const uint4*)(g_win_h16 + (size_t)(f0 + fi) * Zd + seg * 8);
            *(uint4*)&smw[O_WIL + fi * STZ + seg * 4] =
                *(const uint4*)(g_win_l16 + (size_t)(f0 + fi) * Zd + seg * 8);
        }
#pragma unroll
        for (int it = 0; it < 4; it++) {
            int idx = t + it * 256;
            int z = idx >> 3, seg = idx & 7;
            *(uint4*)&smw[O_WOTH + z * STG + seg * 4] =
                *(const uint4*)(g_woT_h16 + (size_t)z * Fd + f0 + seg * 8);
            *(uint4*)&smw[O_WOTL + z * STG + seg * 4] =
                *(const uint4*)(g_woT_l16 + (size_t)z * Fd + f0 + seg * 8);
        }
        __syncthreads();

        // ---- GEMM1 ----
        float c1[2][4];
#pragma unroll
        for (int j = 0; j < 2; j++)
#pragma unroll
            for (int q = 0; q < 4; q++) c1[j][q] = 0.f;

#pragma unroll
        for (int kk = 0; kk < 8; kk++) {
            uint32_t ah[4], al[4], bh[4], bl[4];
            ldsm_x4(ah, aZH + kk * 32);
            ldsm_x4(al, aZL + kk * 32);
            ldsm_x4(bh, bWH + kk * 32);
            ldsm_x4(bl, bWL + kk * 32);
#pragma unroll
            for (int j = 0; j < 2; j++) {
                mma_bf16(c1[j], ah, bh + 2 * j);
                mma_bf16(c1[j], al, bh + 2 * j);
                mma_bf16(c1[j], ah, bl + 2 * j);
            }
        }

        // ---- epilogue ----
#pragma unroll
        for (int j = 0; j < 2; j++) {
            const int fc = f0 + wc * 16 + j * 8 + 2 * tq;
            const float2 bi = __ldg((const float2*)(g_bias + fc));
            const float2 ga = __ldg((const float2*)(g_gate + fc));
            const float2 gs = __ldg((const float2*)(g_gs + fc));
            const int r  = wr * 16 + g;
            const int cw = wc * 8 + j * 4 + tq;
            {
                float h0 = fast_tanh(c1[j][0] + bi.x);
                float h1 = fast_tanh(c1[j][1] + bi.y);
                tracc[0] += (1.f - h0 * h0) * gs.x + (1.f - h1 * h1) * gs.y;
                uint32_t lo, hi = pack_split(h0 * ga.x, h1 * ga.y, lo);
                smw[O_GHI + r * STG + cw] = hi;
                smw[O_GLO + r * STG + cw] = lo;
            }
            {
                float h2 = fast_tanh(c1[j][2] + bi.x);
                float h3 = fast_tanh(c1[j][3] + bi.y);
                tracc[1] += (1.f - h2 * h2) * gs.x + (1.f - h3 * h3) * gs.y;
                uint32_t lo, hi = pack_split(h2 * ga.x, h3 * ga.y, lo);
                smw[O_GHI + (r + 8) * STG + cw] = hi;
                smw[O_GLO + (r + 8) * STG + cw] = lo;
            }
        }
        __syncthreads();

        // ---- GEMM2 ----
#pragma unroll
        for (int kk = 0; kk < 4; kk++) {
            uint32_t ah[4], al[4], bo_h[8], bo_l[8];
            ldsm_x4(ah, aGH + kk * 32);
            ldsm_x4(al, aGL + kk * 32);
            ldsm_x4(bo_h,     bOH0 + kk * 32);
            ldsm_x4(bo_h + 4, bOH1 + kk * 32);
            ldsm_x4(bo_l,     bOL0 + kk * 32);
            ldsm_x4(bo_l + 4, bOL1 + kk * 32);
#pragma unroll
            for (int jn = 0; jn < 4; jn++) {
                mma_bf16(dz[jn], ah, bo_h + 2 * jn);
                mma_bf16(dz[jn], al, bo_h + 2 * jn);
                mma_bf16(dz[jn], ah, bo_l + 2 * jn);
            }
        }
    }

    // ---- accumulate dz into out (chunk 0 writes, others add) ----
    const float invF = 1.0f / (float)Fd;
#pragma unroll
    for (int jn = 0; jn < 4; jn++) {
        const int r  = b0 + wr * 16 + g;
        const int z0 = wc * 32 + jn * 8 + 2 * tq;
        size_t i0 = (size_t)r * OSTRIDE + z0;
        size_t i1 = (size_t)(r + 8) * OSTRIDE + z0;
        if (chunk == 0) {
            out[i0]     = dz[jn][0] * invF;
            out[i0 + 1] = dz[jn][1] * invF;
            out[i1]     = dz[jn][2] * invF;
            out[i1 + 1] = dz[jn][3] * invF;
        } else {
            out[i0]     += dz[jn][0] * invF;
            out[i0 + 1] += dz[jn][1] * invF;
            out[i1]     += dz[jn][2] * invF;
            out[i1 + 1] += dz[jn][3] * invF;
        }
    }

    // ---- trace reduction ----
    tracc[0] += __shfl_xor_sync(0xFFFFFFFFu, tracc[0], 1);
    tracc[0] += __shfl_xor_sync(0xFFFFFFFFu, tracc[0], 2);
    tracc[1] += __shfl_xor_sync(0xFFFFFFFFu, tracc[1], 1);
    tracc[1] += __shfl_xor_sync(0xFFFFFFFFu, tracc[1], 2);
    if (tq == 0) {
        smf[O_TRS + (wr * 16 + g) * 4 + wc]     = tracc[0];
        smf[O_TRS + (wr * 16 + g + 8) * 4 + wc] = tracc[1];
    }
    __syncthreads();
    if (t < TMr) {
        float s = smf[O_TRS + t * 4 + 0] + smf[O_TRS + t * 4 + 1] +
                  smf[O_TRS + t * 4 + 2] + smf[O_TRS + t * 4 + 3];
        size_t idx = (size_t)(b0 + t) * OSTRIDE + Zd;
        if (chunk == 0) out[idx] = -s * invF;
        else            out[idx] -= s * invF;
    }
}

// ---------------- launch: fork-join pipeline over F chunks ----------------
extern "C" void kernel_launch(void* const* d_in, const int* in_sizes, int n_in,
                              void* d_out, int out_size) {
    const float* t       = (const float*)d_in[0];
    const float* zlp     = (const float*)d_in[1];
    const float* W1      = (const float*)d_in[2];
    const float* B1      = (const float*)d_in[3];
    const float* W2      = (const float*)d_in[4];
    const float* B2      = (const float*)d_in[5];
    const float* W3_win  = (const float*)d_in[6];
    const float* b3_win  = (const float*)d_in[7];
    const float* W3_wout = (const float*)d_in[8];
    const float* b3_wout = (const float*)d_in[9];
    const float* W3_b    = (const float*)d_in[10];
    const float* b3_b    = (const float*)d_in[11];
    const float* W3_gate = (const float*)d_in[12];
    const float* b3_gate = (const float*)d_in[13];
    float* out = (float*)d_out;

    cudaFuncSetAttribute(k_tc, cudaFuncAttributeMaxDynamicSharedMemorySize, SMEM_TC);

    int plo = 0, phi = 0;
    cudaDeviceGetStreamPriorityRange(&plo, &phi);
    cudaStream_t s1;
    cudaStreamCreateWithPriority(&s1, cudaStreamNonBlocking, phi);
    cudaEvent_t ev[NCH], evj;
    for (int c = 0; c < NCH; c++) cudaEventCreateWithFlags(&ev[c], cudaEventDisableTiming);
    cudaEventCreateWithFlags(&evj, cudaEventDisableTiming);

    k_h1<<<32, 256>>>(t, W1, B1, W2, B2);

    for (int c = 0; c < NCH; c++) {
        k_wproj<<<2 * FCH * Zd / 8, 256>>>(c, W3_win, b3_win, W3_wout, b3_wout);  // 16384 blocks
        k_split<<<FCH * Zd / 256, 256>>>(c);
        k_small<<<FCH / 4, 128>>>(c, W3_b, b3_b, W3_gate, b3_gate);
        cudaEventRecord(ev[c], 0);
        cudaStreamWaitEvent(s1, ev[c], 0);
        k_tc<<<Bd / TMr, 256, SMEM_TC, s1>>>(c, zlp, out);
    }

    cudaEventRecord(evj, s1);
    cudaStreamWaitEvent(0, evj, 0);
    // streams/events intentionally leaked: kernel_launch is called only a
    // handful of times (correctness + capture) and cleanup during capture
    // is unsafe; no device memory is involved.
}

// round 12
// speedup vs baseline: 1.3162x; 1.3162x over previous
#include <cuda_runtime.h>
#include <cuda_fp16.h>
#include <math.h>
#include <stdint.h>

#define Zd  128
#define Nd  256
#define Fd  2048
#define Bd  8192
#define OSTRIDE 129   // Z+1

#define TMr 32        // batch rows per CTA
#define BF  64        // f tile
#define NT  (Fd / BF) // 32 tiles

// ---------------- device scratch ----------------
__device__ float g_h1[4][Nd];
__device__ float g_win  [Fd * Zd];
__device__ float g_wout [Fd * Zd];
__device__ float g_woutT[Zd * Fd];
__device__ float g_bias[Fd];
__device__ float g_gate[Fd];
__device__ float g_gs  [Fd];
// fp16 weights (made by k_split)
__device__ __align__(16) uint16_t g_win_h16[Fd * Zd];   // [f][z]  fp16(w_in)
__device__ __align__(16) uint16_t g_woT_h16[Zd * Fd];   // [z][f]  fp16(w_out^T)

// ---------------- smem word layout (strides ≡ 4 mod 32, rows 16B-aligned) ----------------
#define STZ 68   // 64 data words + 4 pad (272 B rows)
#define STG 36   // 32 data words + 4 pad (144 B rows)
#define O_ZHI   0
#define O_ZLO   (O_ZHI  + TMr * STZ)
#define O_WIH   (O_ZLO  + TMr * STZ)
#define O_WOTH  (O_WIH  + BF * STZ)
#define O_GHI   (O_WOTH + Zd * STG)
#define O_GLO   (O_GHI  + TMr * STG)
#define O_TRS   (O_GLO  + TMr * STG)
#define SMEMW   (O_TRS  + TMr * 4)
#define SMEM_TC (SMEMW * 4)          // ~63 KB

// ---------------- helpers ----------------
__device__ __forceinline__ uint32_t smem_u32(const void* p) {
    uint32_t a;
    asm("{ .reg .u64 t; cvta.to.shared.u64 t, %1; cvt.u32.u64 %0, t; }" : "=r"(a) : "l"(p));
    return a;
}
__device__ __forceinline__ void ldsm_x4(uint32_t* r, uint32_t addr) {
    asm volatile("ldmatrix.sync.aligned.m8n8.x4.shared.b16 {%0,%1,%2,%3}, [%4];"
                 : "=r"(r[0]), "=r"(r[1]), "=r"(r[2]), "=r"(r[3]) : "r"(addr));
}

// fp16 split: a = ah + al (al captures next 11 bits); pack two values per word
__device__ __forceinline__ uint32_t pack_split_f16(float a, float b, uint32_t& lopack) {
    __half ah = __float2half_rn(a);
    __half bh = __float2half_rn(b);
    __half al = __float2half_rn(a - __half2float(ah));
    __half bl = __float2half_rn(b - __half2float(bh));
    lopack = (uint32_t)__half_as_ushort(al) | ((uint32_t)__half_as_ushort(bl) << 16);
    return (uint32_t)__half_as_ushort(ah) | ((uint32_t)__half_as_ushort(bh) << 16);
}

__device__ __forceinline__ float fast_tanh(float x) {
    float ax = fabsf(x);
    float e;
    asm("ex2.approx.f32 %0, %1;" : "=f"(e) : "f"(ax * 2.8853900817779268f));
    float r;
    asm("rcp.approx.f32 %0, %1;" : "=f"(r) : "f"(e + 1.0f));
    return copysignf(1.0f - 2.0f * r, x);
}

__device__ __forceinline__ void mma_f16(float* c, const uint32_t* a, const uint32_t* b) {
    asm volatile(
        "mma.sync.aligned.m16n8k16.row.col.f32.f16.f16.f32 "
        "{%0,%1,%2,%3}, {%4,%5,%6,%7}, {%8,%9}, {%0,%1,%2,%3};"
        : "+f"(c[0]), "+f"(c[1]), "+f"(c[2]), "+f"(c[3])
        : "r"(a[0]), "r"(a[1]), "r"(a[2]), "r"(a[3]), "r"(b[0]), "r"(b[1]));
}

// ---------------- kernel 1: hypernet h0 -> h1 (32 blocks) ----------------
__global__ void k_h1(const float* __restrict__ tt,
                     const float* __restrict__ W1, const float* __restrict__ B1,
                     const float* __restrict__ W2, const float* __restrict__ B2) {
    __shared__ float h0[Nd];
    const int k   = blockIdx.x >> 3;
    const int blk = blockIdx.x & 7;
    const int t   = threadIdx.x;
    const float ts = tt[0];
    h0[t] = tanhf(fmaf(W1[k * Nd + t], ts, B1[k * Nd + t]));
    __syncthreads();

    const int wid  = t >> 5;
    const int lane = t & 31;
    const float4* h4 = (const float4*)h0;
#pragma unroll
    for (int r = 0; r < 4; r++) {
        const int n = blk * 32 + wid * 4 + r;
        const float4* w2 = (const float4*)(W2 + ((size_t)k * Nd + n) * Nd);
        float acc = 0.f;
#pragma unroll
        for (int i = 0; i < 2; i++) {
            float4 v = w2[lane + i * 32];
            float4 h = h4[lane + i * 32];
            acc = fmaf(v.x, h.x, fmaf(v.y, h.y, fmaf(v.z, h.z, fmaf(v.w, h.w, acc))));
        }
#pragma unroll
        for (int o = 16; o > 0; o >>= 1) acc += __shfl_xor_sync(0xFFFFFFFFu, acc, o);
        if (lane == 0) g_h1[k][n] = tanhf(acc + B2[k * Nd + n]);
    }
}

// ---------------- kernel 2: w_in / w_out matvecs ----------------
__global__ void k_wproj(const float* __restrict__ W3_win,  const float* __restrict__ b3_win,
                        const float* __restrict__ W3_wout, const float* __restrict__ b3_wout) {
    __shared__ float h1a[Nd], h1b[Nd];
    const int t = threadIdx.x;
    h1a[t] = g_h1[0][t];
    h1b[t] = g_h1[1][t];
    __syncthreads();

    const int wid  = t >> 5;
    const int lane = t & 31;
    long r = (long)blockIdx.x * 8 + wid;

    const float* wmat; const float* bias; const float* hv; long rr; int isOut;
    if (r < (long)Fd * Zd) { rr = r;                 wmat = W3_win;  bias = b3_win;  hv = h1a; isOut = 0; }
    else                   { rr = r - (long)Fd * Zd; wmat = W3_wout; bias = b3_wout; hv = h1b; isOut = 1; }

    const float4* __restrict__ row = (const float4*)(wmat + rr * Nd);
    const float4* __restrict__ hv4 = (const float4*)hv;
    float acc = 0.f;
#pragma unroll
    for (int i = 0; i < 2; i++) {
        float4 v = row[lane + i * 32];
        float4 h = hv4[lane + i * 32];
        acc = fmaf(v.x, h.x, acc);
        acc = fmaf(v.y, h.y, acc);
        acc = fmaf(v.z, h.z, acc);
        acc = fmaf(v.w, h.w, acc);
    }
#pragma unroll
    for (int o = 16; o > 0; o >>= 1) acc += __shfl_xor_sync(0xFFFFFFFFu, acc, o);
    if (lane == 0) {
        float v = acc + bias[rr];
        if (isOut) {
            g_wout[rr] = v;
            int f = (int)(rr >> 7);
            int z = (int)(rr & 127);
            g_woutT[(size_t)z * Fd + f] = v;
        } else {
            g_win[rr] = v;
        }
    }
}

// ---------------- k_split: fp16 weight conversion ----------------
__global__ void k_split() {
    int idx = blockIdx.x * 256 + threadIdx.x;
    g_win_h16[idx] = __half_as_ushort(__float2half_rn(g_win[idx]));
    g_woT_h16[idx] = __half_as_ushort(__float2half_rn(g_woutT[idx]));
}

// ---------------- kernel 3: bias, gate, gate*s ----------------
__global__ void k_small(const float* __restrict__ W3_b,    const float* __restrict__ b3_b,
                        const float* __restrict__ W3_gate, const float* __restrict__ b3_gate) {
    __shared__ float h2[Nd], h3[Nd];
    const int t = threadIdx.x;
    h2[t] = g_h1[2][t];  h2[t + 128] = g_h1[2][t + 128];
    h3[t] = g_h1[3][t];  h3[t + 128] = g_h1[3][t + 128];
    __syncthreads();

    const int wid  = t >> 5;
    const int lane = t & 31;
    const int f = blockIdx.x * 4 + wid;

    const float4* rb = (const float4*)(W3_b    + (size_t)f * Nd);
    const float4* rg = (const float4*)(W3_gate + (size_t)f * Nd);
    const float4* h2v = (const float4*)h2;
    const float4* h3v = (const float4*)h3;

    float accb = 0.f, accg = 0.f;
#pragma unroll
    for (int i = 0; i < 2; i++) {
        float4 v = rb[lane + i * 32], h = h2v[lane + i * 32];
        accb = fmaf(v.x, h.x, fmaf(v.y, h.y, fmaf(v.z, h.z, fmaf(v.w, h.w, accb))));
        float4 v2 = rg[lane + i * 32], h4 = h3v[lane + i * 32];
        accg = fmaf(v2.x, h4.x, fmaf(v2.y, h4.y, fmaf(v2.z, h4.z, fmaf(v2.w, h4.w, accg))));
    }
    const float4 a  = ((const float4*)(g_win  + (size_t)f * Zd))[lane];
    const float4 b4 = ((const float4*)(g_wout + (size_t)f * Zd))[lane];
    float accs = a.x * b4.x + a.y * b4.y + a.z * b4.z + a.w * b4.w;

#pragma unroll
    for (int o = 16; o > 0; o >>= 1) {
        accb += __shfl_xor_sync(0xFFFFFFFFu, accb, o);
        accg += __shfl_xor_sync(0xFFFFFFFFu, accg, o);
        accs += __shfl_xor_sync(0xFFFFFFFFu, accs, o);
    }
    if (lane == 0) {
        g_bias[f] = accb + b3_b[f];
        float gt = 1.f / (1.f + expf(-(accg + b3_gate[f])));
        g_gate[f] = gt;
        g_gs[f]   = gt * accs;
    }
}

// ---------------- k_tc: fp16 split-activation mma.sync double GEMM ----------------
__global__ __launch_bounds__(256, 2)
void k_tc(const float* __restrict__ zlp, float* __restrict__ out) {
    extern __shared__ uint32_t smw[];
    float* smf = (float*)smw;
    const uint32_t sb = smem_u32(smw);

    const int t    = threadIdx.x;
    const int lane = t & 31;
    const int wid  = t >> 5;
    const int g    = lane >> 2;
    const int tq   = lane & 3;
    const int wr   = wid >> 2;       // 0..1
    const int wc   = wid & 3;        // 0..3
    const int b0   = blockIdx.x * TMr;

    const int rowA  = lane & 15;
    const int aofs  = ((lane >> 4) & 1) * 16;
    const int rowB  = (lane & 7) + ((lane >> 4) & 1) * 8;
    const int bofs  = ((lane >> 3) & 1) * 16;

    const uint32_t aZH = sb + O_ZHI * 4 + (wr * 16 + rowA) * (STZ * 4) + aofs;
    const uint32_t aZL = sb + O_ZLO * 4 + (wr * 16 + rowA) * (STZ * 4) + aofs;
    const uint32_t bWH = sb + O_WIH * 4 + (wc * 16 + rowB) * (STZ * 4) + bofs;
    const uint32_t aGH = sb + O_GHI * 4 + (wr * 16 + rowA) * (STG * 4) + aofs;
    const uint32_t aGL = sb + O_GLO * 4 + (wr * 16 + rowA) * (STG * 4) + aofs;
    const uint32_t bOH0 = sb + O_WOTH * 4 + (wc * 32 + rowB) * (STG * 4) + bofs;
    const uint32_t bOH1 = bOH0 + 16 * (STG * 4);

    // ---- stage z (hi/lo fp16), once ----
#pragma unroll
    for (int it = 0; it < 8; it++) {
        int idx = t + it * 256;
        int m = idx >> 6, kp = idx & 63;
        const float* zr = zlp + (size_t)(b0 + m) * OSTRIDE + 2 * kp;
        uint32_t lo, hi = pack_split_f16(zr[0], zr[1], lo);
        smw[O_ZHI + m * STZ + kp] = hi;
        smw[O_ZLO + m * STZ + kp] = lo;
    }

    float dz[4][4];
#pragma unroll
    for (int j = 0; j < 4; j++)
#pragma unroll
        for (int q = 0; q < 4; q++) dz[j][q] = 0.f;
    float tracc[2] = {0.f, 0.f};

    for (int tile = 0; tile < NT; tile++) {
        const int f0 = tile * BF;
        __syncthreads();

        // ---- stage w_in tile: 64 f x 16 uint4 (fp16) ----
#pragma unroll
        for (int it = 0; it < 4; it++) {
            int idx = t + it * 256;            // 0..1023
            int fi = idx >> 4, seg = idx & 15;
            *(uint4*)&smw[O_WIH + fi * STZ + seg * 4] =
                *(const uint4*)(g_win_h16 + (size_t)(f0 + fi) * Zd + seg * 8);
        }
        // ---- stage w_outT tile: 128 z x 8 uint4 (fp16) ----
#pragma unroll
        for (int it = 0; it < 4; it++) {
            int idx = t + it * 256;            // 0..1023
            int z = idx >> 3, seg = idx & 7;
            *(uint4*)&smw[O_WOTH + z * STG + seg * 4] =
                *(const uint4*)(g_woT_h16 + (size_t)z * Fd + f0 + seg * 8);
        }
        __syncthreads();

        // ---- GEMM1: c1 = (zh+zl) @ wh^T  (32x64; warp tile 16m x 16f) ----
        float c1[2][4];
#pragma unroll
        for (int j = 0; j < 2; j++)
#pragma unroll
            for (int q = 0; q < 4; q++) c1[j][q] = 0.f;

#pragma unroll
        for (int kk = 0; kk < 8; kk++) {
            uint32_t ah[4], al[4], bh[4];
            ldsm_x4(ah, aZH + kk * 32);
            ldsm_x4(al, aZL + kk * 32);
            ldsm_x4(bh, bWH + kk * 32);   // (j0,k0)(j0,k8)(j1,k0)(j1,k8)
#pragma unroll
            for (int j = 0; j < 2; j++) {
                mma_f16(c1[j], ah, bh + 2 * j);
                mma_f16(c1[j], al, bh + 2 * j);
            }
        }

        // ---- epilogue: tanh/gate/trace, stage g (hi/lo fp16) ----
#pragma unroll
        for (int j = 0; j < 2; j++) {
            const int fc = f0 + wc * 16 + j * 8 + 2 * tq;
            const float2 bi = __ldg((const float2*)(g_bias + fc));
            const float2 ga = __ldg((const float2*)(g_gate + fc));
            const float2 gs = __ldg((const float2*)(g_gs + fc));
            const int r  = wr * 16 + g;
            const int cw = wc * 8 + j * 4 + tq;
            {
                float h0 = fast_tanh(c1[j][0] + bi.x);
                float h1 = fast_tanh(c1[j][1] + bi.y);
                tracc[0] += (1.f - h0 * h0) * gs.x + (1.f - h1 * h1) * gs.y;
                uint32_t lo, hi = pack_split_f16(h0 * ga.x, h1 * ga.y, lo);
                smw[O_GHI + r * STG + cw] = hi;
                smw[O_GLO + r * STG + cw] = lo;
            }
            {
                float h2 = fast_tanh(c1[j][2] + bi.x);
                float h3 = fast_tanh(c1[j][3] + bi.y);
                tracc[1] += (1.f - h2 * h2) * gs.x + (1.f - h3 * h3) * gs.y;
                uint32_t lo, hi = pack_split_f16(h2 * ga.x, h3 * ga.y, lo);
                smw[O_GHI + (r + 8) * STG + cw] = hi;
                smw[O_GLO + (r + 8) * STG + cw] = lo;
            }
        }
        __syncthreads();

        // ---- GEMM2: dz += (gh+gl) @ wo_h (32m x 128z; warp 16m x 32z, k=64) ----
#pragma unroll
        for (int kk = 0; kk < 4; kk++) {
            uint32_t ah[4], al[4], bo_h[8];
            ldsm_x4(ah, aGH + kk * 32);
            ldsm_x4(al, aGL + kk * 32);
            ldsm_x4(bo_h,     bOH0 + kk * 32);
            ldsm_x4(bo_h + 4, bOH1 + kk * 32);
#pragma unroll
            for (int jn = 0; jn < 4; jn++) {
                mma_f16(dz[jn], ah, bo_h + 2 * jn);
                mma_f16(dz[jn], al, bo_h + 2 * jn);
            }
        }
    }

    // ---- write dz ----
    const float invF = 1.0f / (float)Fd;
#pragma unroll
    for (int jn = 0; jn < 4; jn++) {
        const int r  = b0 + wr * 16 + g;
        const int z0 = wc * 32 + jn * 8 + 2 * tq;
        out[(size_t)r * OSTRIDE + z0]           = dz[jn][0] * invF;
        out[(size_t)r * OSTRIDE + z0 + 1]       = dz[jn][1] * invF;
        out[(size_t)(r + 8) * OSTRIDE + z0]     = dz[jn][2] * invF;
        out[(size_t)(r + 8) * OSTRIDE + z0 + 1] = dz[jn][3] * invF;
    }

    // ---- trace reduction ----
    tracc[0] += __shfl_xor_sync(0xFFFFFFFFu, tracc[0], 1);
    tracc[0] += __shfl_xor_sync(0xFFFFFFFFu, tracc[0], 2);
    tracc[1] += __shfl_xor_sync(0xFFFFFFFFu, tracc[1], 1);
    tracc[1] += __shfl_xor_sync(0xFFFFFFFFu, tracc[1], 2);
    if (tq == 0) {
        smf[O_TRS + (wr * 16 + g) * 4 + wc]     = tracc[0];
        smf[O_TRS + (wr * 16 + g + 8) * 4 + wc] = tracc[1];
    }
    __syncthreads();
    if (t < TMr) {
        float s = smf[O_TRS + t * 4 + 0] + smf[O_TRS + t * 4 + 1] +
                  smf[O_TRS + t * 4 + 2] + smf[O_TRS + t * 4 + 3];
        out[(size_t)(b0 + t) * OSTRIDE + Zd] = -s * invF;
    }
}

// ---------------- launch ----------------
extern "C" void kernel_launch(void* const* d_in, const int* in_sizes, int n_in,
                              void* d_out, int out_size) {
    const float* t       = (const float*)d_in[0];
    const float* zlp     = (const float*)d_in[1];
    const float* W1      = (const float*)d_in[2];
    const float* B1      = (const float*)d_in[3];
    const float* W2      = (const float*)d_in[4];
    const float* B2      = (const float*)d_in[5];
    const float* W3_win  = (const float*)d_in[6];
    const float* b3_win  = (const float*)d_in[7];
    const float* W3_wout = (const float*)d_in[8];
    const float* b3_wout = (const float*)d_in[9];
    const float* W3_b    = (const float*)d_in[10];
    const float* b3_b    = (const float*)d_in[11];
    const float* W3_gate = (const float*)d_in[12];
    const float* b3_gate = (const float*)d_in[13];
    float* out = (float*)d_out;

    cudaFuncSetAttribute(k_tc, cudaFuncAttributeMaxDynamicSharedMemorySize, SMEM_TC);

    k_h1   <<<32,    256>>>(t, W1, B1, W2, B2);
    k_wproj<<<65536, 256>>>(W3_win, b3_win, W3_wout, b3_wout);
    k_split<<<Fd * Zd / 256, 256>>>();
    k_small<<<512,   128>>>(W3_b, b3_b, W3_gate, b3_gate);
    k_tc   <<<Bd / TMr, 256, SMEM_TC>>>(zlp, out);
}